// round 9
// baseline (speedup 1.0000x reference)
#include <cuda_runtime.h>

typedef unsigned long long u64;

#define N_EDGES_CAP 160000
__device__ float g_mix[(size_t)N_EDGES_CAP * 256];

#define TE 64
#define TPB_A 128
#define SMEM_A_FLOATS 12288   // sA(4096) + sB(4096) + sW(4096)

// ---------- packed f32x2 helpers ----------
__device__ __forceinline__ u64 pack2(float a, float b) {
    u64 r; asm("mov.b64 %0, {%1, %2};" : "=l"(r) : "f"(a), "f"(b)); return r;
}
__device__ __forceinline__ u64 bcast2(float a) { return pack2(a, a); }
__device__ __forceinline__ u64 ffma2(u64 a, u64 b, u64 c) {
    u64 d; asm("fma.rn.f32x2 %0, %1, %2, %3;" : "=l"(d) : "l"(a), "l"(b), "l"(c)); return d;
}
__device__ __forceinline__ void unpack2(float& lo, float& hi, u64 v) {
    asm("mov.b64 {%0, %1}, %2;" : "=f"(lo), "=f"(hi) : "l"(v));
}

__device__ __forceinline__ void red4(float* p, float a, float b, float c, float d) {
    asm volatile("red.global.add.v4.f32 [%0], {%1, %2, %3, %4};"
                 :: "l"(p), "f"(a), "f"(b), "f"(c), "f"(d) : "memory");
}

__device__ __forceinline__ float silu(float x) {
    return __fdividef(x, 1.0f + __expf(-x));
}

// GEMM: C[4 edges][8 cols] += sIn[k][e] * sWt[k][j]
template<int K>
__device__ __forceinline__ void gemm16(const float* __restrict__ sIn,
                                       const float* __restrict__ sWt,
                                       int eoff, int joff, u64 (&acc)[16])
{
    #pragma unroll
    for (int m = 0; m < 16; m++) acc[m] = 0ull;
    #pragma unroll 8
    for (int k = 0; k < K; k++) {
        float4 av = *(const float4*)(sIn + k * 64 + eoff);
        const ulonglong2* bp = (const ulonglong2*)(sWt + k * 64 + joff);
        ulonglong2 b0 = bp[0], b1 = bp[1];
        u64 a0 = bcast2(av.x), a1 = bcast2(av.y), a2 = bcast2(av.z), a3 = bcast2(av.w);
        acc[0]  = ffma2(a0, b0.x, acc[0]);
        acc[1]  = ffma2(a0, b0.y, acc[1]);
        acc[2]  = ffma2(a0, b1.x, acc[2]);
        acc[3]  = ffma2(a0, b1.y, acc[3]);
        acc[4]  = ffma2(a1, b0.x, acc[4]);
        acc[5]  = ffma2(a1, b0.y, acc[5]);
        acc[6]  = ffma2(a1, b1.x, acc[6]);
        acc[7]  = ffma2(a1, b1.y, acc[7]);
        acc[8]  = ffma2(a2, b0.x, acc[8]);
        acc[9]  = ffma2(a2, b0.y, acc[9]);
        acc[10] = ffma2(a2, b1.x, acc[10]);
        acc[11] = ffma2(a2, b1.y, acc[11]);
        acc[12] = ffma2(a3, b0.x, acc[12]);
        acc[13] = ffma2(a3, b0.y, acc[13]);
        acc[14] = ffma2(a3, b1.x, acc[14]);
        acc[15] = ffma2(a3, b1.y, acc[15]);
    }
}

// Epilogue: silu(acc*scale)*post, store TRANSPOSED sOut[j][e].
__device__ __forceinline__ void silu_store_T(u64 (&acc)[16], float scale, float post,
                                             float* __restrict__ sOut, int eoff, int joff)
{
    float c[4][8];
    #pragma unroll
    for (int ei = 0; ei < 4; ei++)
        #pragma unroll
        for (int jp = 0; jp < 4; jp++)
            unpack2(c[ei][2*jp], c[ei][2*jp+1], acc[ei*4 + jp]);
    #pragma unroll
    for (int ei = 0; ei < 4; ei++)
        #pragma unroll
        for (int jj = 0; jj < 8; jj++)
            c[ei][jj] = silu(c[ei][jj] * scale) * post;
    #pragma unroll
    for (int jj = 0; jj < 8; jj++) {
        float4 v = make_float4(c[0][jj], c[1][jj], c[2][jj], c[3][jj]);
        *(float4*)(sOut + (joff + jj) * 64 + eoff) = v;
    }
}

// Layer-4 epilogue: store untransposed [e][j] into the staging tile.
__device__ __forceinline__ void store_mix(u64 (&acc)[16], float* __restrict__ sOut,
                                          int eoff, int joff)
{
    #pragma unroll
    for (int ei = 0; ei < 4; ei++) {
        float4 v0, v1;
        unpack2(v0.x, v0.y, acc[ei*4 + 0]);
        unpack2(v0.z, v0.w, acc[ei*4 + 1]);
        unpack2(v1.x, v1.y, acc[ei*4 + 2]);
        unpack2(v1.z, v1.w, acc[ei*4 + 3]);
        *(float4*)(sOut + (eoff + ei) * 64 + joff)     = v0;
        *(float4*)(sOut + (eoff + ei) * 64 + joff + 4) = v1;
    }
}

// ===================== Kernel A: tiled-GEMM radial MLP -> mix (chunked) =====================
__global__ void __launch_bounds__(TPB_A)
mlp_kernel(const float* __restrict__ radial,
           const float* __restrict__ w1, const float* __restrict__ w2,
           const float* __restrict__ w3, const float* __restrict__ w4,
           int e_base, int e_end)
{
    extern __shared__ float smem[];
    float* sA = smem;          // 4096 floats
    float* sB = smem + 4096;   // 4096
    float* sW = smem + 8192;   // 4096

    int tid = threadIdx.x;
    int e0 = e_base + blockIdx.x * TE;
    int eoff = (tid & 15) * 4;
    int joff = (tid >> 4) * 8;

    // stage radial transposed into sA[k][e] (k<8), zero-fill tail edges
    {
        int e  = tid >> 1;
        int kh = (tid & 1) * 4;
        int ge = e0 + e;
        float4 v = make_float4(0.f, 0.f, 0.f, 0.f);
        if (ge < e_end) v = *(const float4*)(radial + (size_t)ge * 8 + kh);
        sA[(kh + 0) * 64 + e] = v.x;
        sA[(kh + 1) * 64 + e] = v.y;
        sA[(kh + 2) * 64 + e] = v.z;
        sA[(kh + 3) * 64 + e] = v.w;
    }
    ((float4*)sW)[tid] = ((const float4*)w1)[tid];
    __syncthreads();

    u64 acc[16];

    // layer 1: K=8, scale 1/sqrt(8)
    gemm16<8>(sA, sW, eoff, joff, acc);
    silu_store_T(acc, 0.35355339059327373f, 1.0f, sB, eoff, joff);
    __syncthreads();

    // layer 2
    #pragma unroll
    for (int i = 0; i < 8; i++)
        ((float4*)sW)[tid + i * TPB_A] = ((const float4*)w2)[tid + i * TPB_A];
    __syncthreads();
    gemm16<64>(sB, sW, eoff, joff, acc);
    silu_store_T(acc, 0.125f, 1.0f, sA, eoff, joff);
    __syncthreads();

    // layer 3: fold (1/8 w4-norm)*(1/sqrt(16)) = 1/32 into h3
    #pragma unroll
    for (int i = 0; i < 8; i++)
        ((float4*)sW)[tid + i * TPB_A] = ((const float4*)w3)[tid + i * TPB_A];
    __syncthreads();
    gemm16<64>(sA, sW, eoff, joff, acc);
    silu_store_T(acc, 0.125f, 0.03125f, sB, eoff, joff);
    __syncthreads();

    // layer 4: mix = h3 @ w4, 4 chunks of 64 output cols; h3 persists in sB
    #pragma unroll 1
    for (int chunk = 0; chunk < 4; chunk++) {
        #pragma unroll
        for (int i = 0; i < 8; i++) {
            int idx = tid + i * TPB_A;
            int row = idx >> 4, col = idx & 15;
            ((float4*)sW)[idx] =
                *(const float4*)(w4 + (size_t)row * 256 + chunk * 64 + col * 4);
        }
        __syncthreads();
        gemm16<64>(sB, sW, eoff, joff, acc);
        store_mix(acc, sA, eoff, joff);
        __syncthreads();
        #pragma unroll
        for (int i = 0; i < 8; i++) {
            int idx = tid + i * TPB_A;
            int row = idx >> 4, col = idx & 15;
            int ge = e0 + row;
            if (ge < e_end)
                *(float4*)(g_mix + (size_t)ge * 256 + chunk * 64 + col * 4) =
                    ((float4*)sA)[idx];
        }
    }
}

// ===================== Kernel B: tensor product + coalesced scatter (chunked) =====================
template<int W, int START, int TB, int YB, int MUL>
__device__ __forceinline__ float tpv(const float* tsh, const float* ysh, int p) {
    int pp = p - START;
    int c = (pp * MUL) >> 16;
    int k = pp - c * W;
    return tsh[TB + c] * ysh[YB + k];
}

#define TPB_B 256

__global__ void __launch_bounds__(TPB_B)
scatter_kernel(const float* __restrict__ vectors,
               const float* __restrict__ node_feats,
               const int* __restrict__ senders,
               const int* __restrict__ receivers,
               float* __restrict__ out, int e_base, int e_end)
{
    __shared__ float stage[TPB_B / 32][272];   // per-warp: t[256] + y[15]
    int warp = threadIdx.x >> 5, lane = threadIdx.x & 31;
    int e = e_base + blockIdx.x * (TPB_B / 32) + warp;
    if (e >= e_end) return;

    float* tsh = stage[warp];
    float* ysh = tsh + 256;

    int snd = __ldg(senders + e), rcv = __ldg(receivers + e);

    // t[c] = node_feats[snd][c & 63] * mix[e][c]
    {
        const float4* mp = (const float4*)(g_mix + (size_t)e * 256) + lane * 2;
        float4 m0 = __ldg(mp), m1 = __ldg(mp + 1);
        const float4* sp = (const float4*)(node_feats + (size_t)snd * 64) + (lane & 7) * 2;
        float4 s0 = __ldg(sp), s1 = __ldg(sp + 1);
        float4 t0 = make_float4(m0.x*s0.x, m0.y*s0.y, m0.z*s0.z, m0.w*s0.w);
        float4 t1 = make_float4(m1.x*s1.x, m1.y*s1.y, m1.z*s1.z, m1.w*s1.w);
        ((float4*)tsh)[lane*2]     = t0;
        ((float4*)tsh)[lane*2 + 1] = t1;
    }

    // spherical harmonics (lane 0 stores 15 floats)
    {
        float vx = __ldg(vectors + 3*(size_t)e + 0);
        float vy = __ldg(vectors + 3*(size_t)e + 1);
        float vz = __ldg(vectors + 3*(size_t)e + 2);
        float inv = 1.0f / (sqrtf(vx*vx + vy*vy + vz*vz) + 1e-12f);
        float x = vx*inv, y = vy*inv, z = vz*inv;
        const float s3  = 1.7320508075688772f;
        const float s5  = 2.23606797749979f;
        const float s15 = 3.872983346207417f;
        const float c33 = 2.091650066335189f;
        const float c32 = 10.246950765959598f;
        const float c31 = 1.6201851746019651f;
        const float c30 = 1.3228756555322954f;
        float z2 = z*z, x2 = x*x, y2 = y*y;
        if (lane == 0) {
            ysh[0]  = s3 * y;  ysh[1] = s3 * z;  ysh[2] = s3 * x;
            ysh[3]  = s15 * x * y;
            ysh[4]  = s15 * y * z;
            ysh[5]  = 0.5f * s5 * (3.0f * z2 - 1.0f);
            ysh[6]  = s15 * x * z;
            ysh[7]  = 0.5f * s15 * (x2 - y2);
            ysh[8]  = c33 * y * (3.0f * x2 - y2);
            ysh[9]  = c32 * x * y * z;
            ysh[10] = c31 * y * (5.0f * z2 - 1.0f);
            ysh[11] = c30 * z * (5.0f * z2 - 3.0f);
            ysh[12] = c31 * x * (5.0f * z2 - 1.0f);
            ysh[13] = 0.5f * c32 * z * (x2 - y2);
            ysh[14] = c33 * x * (x2 - 3.0f * y2);
        }
    }
    __syncwarp();

    float* ob = out + (size_t)rcv * 1024;

    #pragma unroll
    for (int j = 0; j < 8; j++) {
        int p0 = j * 128 + lane * 4;
        float v0, v1, v2, v3;
        if (j == 0) {
            if (lane < 16) {
                v0 = tsh[p0]; v1 = tsh[p0+1]; v2 = tsh[p0+2]; v3 = tsh[p0+3];
            } else {
                v0 = tpv<3,64,64,0,21846>(tsh, ysh, p0);
                v1 = tpv<3,64,64,0,21846>(tsh, ysh, p0+1);
                v2 = tpv<3,64,64,0,21846>(tsh, ysh, p0+2);
                v3 = tpv<3,64,64,0,21846>(tsh, ysh, p0+3);
            }
        } else if (j == 1) {
            v0 = tpv<3,64,64,0,21846>(tsh, ysh, p0);
            v1 = tpv<3,64,64,0,21846>(tsh, ysh, p0+1);
            v2 = tpv<3,64,64,0,21846>(tsh, ysh, p0+2);
            v3 = tpv<3,64,64,0,21846>(tsh, ysh, p0+3);
        } else if (j == 2 || j == 3) {
            v0 = tpv<5,256,128,3,13108>(tsh, ysh, p0);
            v1 = tpv<5,256,128,3,13108>(tsh, ysh, p0+1);
            v2 = tpv<5,256,128,3,13108>(tsh, ysh, p0+2);
            v3 = tpv<5,256,128,3,13108>(tsh, ysh, p0+3);
        } else if (j == 4) {
            if (lane < 16) {
                v0 = tpv<5,256,128,3,13108>(tsh, ysh, p0);
                v1 = tpv<5,256,128,3,13108>(tsh, ysh, p0+1);
                v2 = tpv<5,256,128,3,13108>(tsh, ysh, p0+2);
                v3 = tpv<5,256,128,3,13108>(tsh, ysh, p0+3);
            } else {
                v0 = tpv<7,576,192,8,9363>(tsh, ysh, p0);
                v1 = tpv<7,576,192,8,9363>(tsh, ysh, p0+1);
                v2 = tpv<7,576,192,8,9363>(tsh, ysh, p0+2);
                v3 = tpv<7,576,192,8,9363>(tsh, ysh, p0+3);
            }
        } else {
            v0 = tpv<7,576,192,8,9363>(tsh, ysh, p0);
            v1 = tpv<7,576,192,8,9363>(tsh, ysh, p0+1);
            v2 = tpv<7,576,192,8,9363>(tsh, ysh, p0+2);
            v3 = tpv<7,576,192,8,9363>(tsh, ysh, p0+3);
        }
        red4(ob + p0, v0, v1, v2, v3);
    }
}

#define NCHUNK 4

extern "C" void kernel_launch(void* const* d_in, const int* in_sizes, int n_in,
                              void* d_out, int out_size)
{
    const float* vectors    = (const float*)d_in[0];
    const float* node_feats = (const float*)d_in[1];
    const float* radial     = (const float*)d_in[2];
    const float* w1         = (const float*)d_in[3];
    const float* w2         = (const float*)d_in[4];
    const float* w3         = (const float*)d_in[5];
    const float* w4         = (const float*)d_in[6];
    const int*   senders    = (const int*)d_in[7];
    const int*   receivers  = (const int*)d_in[8];
    float* out = (float*)d_out;

    int n_edges = in_sizes[7];

    // one-time host-side resources (no device memory)
    static cudaStream_t s2 = nullptr;
    static cudaEvent_t evFork, evDone, evA[NCHUNK];
    if (s2 == nullptr) {
        cudaStreamCreateWithFlags(&s2, cudaStreamNonBlocking);
        cudaEventCreateWithFlags(&evFork, cudaEventDisableTiming);
        cudaEventCreateWithFlags(&evDone, cudaEventDisableTiming);
        for (int i = 0; i < NCHUNK; i++)
            cudaEventCreateWithFlags(&evA[i], cudaEventDisableTiming);
    }

    cudaFuncSetAttribute(mlp_kernel,
                         cudaFuncAttributeMaxDynamicSharedMemorySize,
                         SMEM_A_FLOATS * sizeof(float));

    // fork s2 from the origin stream, zero out on s2 (overlaps first mlp chunk)
    cudaEventRecord(evFork, 0);
    cudaStreamWaitEvent(s2, evFork, 0);
    cudaMemsetAsync(d_out, 0, (size_t)out_size * sizeof(float), s2);

    // chunk size: multiple of TE
    int per = ((n_edges + NCHUNK - 1) / NCHUNK + TE - 1) / TE * TE;

    for (int c = 0; c < NCHUNK; c++) {
        int base = c * per;
        if (base >= n_edges) break;
        int end = base + per;
        if (end > n_edges) end = n_edges;
        int len = end - base;

        int grid_a = (len + TE - 1) / TE;
        mlp_kernel<<<grid_a, TPB_A, SMEM_A_FLOATS * sizeof(float)>>>(
            radial, w1, w2, w3, w4, base, end);
        cudaEventRecord(evA[c], 0);

        cudaStreamWaitEvent(s2, evA[c], 0);
        int epb = TPB_B / 32;
        int grid_b = (len + epb - 1) / epb;
        scatter_kernel<<<grid_b, TPB_B, 0, s2>>>(
            vectors, node_feats, senders, receivers, out, base, end);
    }

    // join s2 back into the origin stream
    cudaEventRecord(evDone, s2);
    cudaStreamWaitEvent(0, evDone, 0);
}

// round 10
// speedup vs baseline: 1.0861x; 1.0861x over previous
#include <cuda_runtime.h>

typedef unsigned long long u64;

#define N_EDGES_CAP 160000
__device__ float g_mix[(size_t)N_EDGES_CAP * 256];

#define TE 64
#define TPB_A 256
// layout (floats): [sA/sMix: 0..4352) [sB: 4352..8448) [sW: 8448..12544)
#define SMEM_A_FLOATS 12544
#define MIX_STRIDE 68

// ---------- packed f32x2 helpers ----------
__device__ __forceinline__ u64 pack2(float a, float b) {
    u64 r; asm("mov.b64 %0, {%1, %2};" : "=l"(r) : "f"(a), "f"(b)); return r;
}
__device__ __forceinline__ u64 bcast2(float a) { return pack2(a, a); }
__device__ __forceinline__ u64 ffma2(u64 a, u64 b, u64 c) {
    u64 d; asm("fma.rn.f32x2 %0, %1, %2, %3;" : "=l"(d) : "l"(a), "l"(b), "l"(c)); return d;
}
__device__ __forceinline__ void unpack2(float& lo, float& hi, u64 v) {
    asm("mov.b64 {%0, %1}, %2;" : "=f"(lo), "=f"(hi) : "l"(v));
}

__device__ __forceinline__ void red4(float* p, float a, float b, float c, float d) {
    asm volatile("red.global.add.v4.f32 [%0], {%1, %2, %3, %4};"
                 :: "l"(p), "f"(a), "f"(b), "f"(c), "f"(d) : "memory");
}

__device__ __forceinline__ float silu(float x) {
    return __fdividef(x, 1.0f + __expf(-x));
}

// GEMM: C[2 edges][8 cols] += sIn[k][e] * sWt[k][j].
// Within a warp joff is uniform -> B loads are broadcast (1 wavefront).
template<int K>
__device__ __forceinline__ void gemm8(const float* __restrict__ sIn,
                                      const float* __restrict__ sWt,
                                      int eoff, int joff, u64 (&acc)[8])
{
    #pragma unroll
    for (int m = 0; m < 8; m++) acc[m] = 0ull;
    #pragma unroll 8
    for (int k = 0; k < K; k++) {
        float2 av = *(const float2*)(sIn + k * 64 + eoff);
        const ulonglong2* bp = (const ulonglong2*)(sWt + k * 64 + joff);
        ulonglong2 b0 = bp[0], b1 = bp[1];
        u64 a0 = bcast2(av.x), a1 = bcast2(av.y);
        acc[0] = ffma2(a0, b0.x, acc[0]);
        acc[1] = ffma2(a0, b0.y, acc[1]);
        acc[2] = ffma2(a0, b1.x, acc[2]);
        acc[3] = ffma2(a0, b1.y, acc[3]);
        acc[4] = ffma2(a1, b0.x, acc[4]);
        acc[5] = ffma2(a1, b0.y, acc[5]);
        acc[6] = ffma2(a1, b1.x, acc[6]);
        acc[7] = ffma2(a1, b1.y, acc[7]);
    }
}

// Epilogue: silu(acc*scale)*post, store TRANSPOSED sOut[j][e] (float2 per col).
__device__ __forceinline__ void epiT8(u64 (&acc)[8], float scale, float post,
                                      float* __restrict__ sOut, int eoff, int joff)
{
    float c0[8], c1[8];
    #pragma unroll
    for (int jp = 0; jp < 4; jp++) {
        unpack2(c0[2*jp], c0[2*jp+1], acc[jp]);
        unpack2(c1[2*jp], c1[2*jp+1], acc[4+jp]);
    }
    #pragma unroll
    for (int jj = 0; jj < 8; jj++) {
        float2 v = make_float2(silu(c0[jj] * scale) * post,
                               silu(c1[jj] * scale) * post);
        *(float2*)(sOut + (joff + jj) * 64 + eoff) = v;
    }
}

// Layer-4 epilogue: raw acc -> sMix[e][MIX_STRIDE]
__device__ __forceinline__ void epiMix8(u64 (&acc)[8], float* __restrict__ sMix,
                                        int eoff, int joff)
{
    #pragma unroll
    for (int e = 0; e < 2; e++) {
        float f[8];
        #pragma unroll
        for (int jp = 0; jp < 4; jp++) unpack2(f[2*jp], f[2*jp+1], acc[e*4 + jp]);
        float* row = sMix + (eoff + e) * MIX_STRIDE + joff;
        *(float4*)(row)     = make_float4(f[0], f[1], f[2], f[3]);
        *(float4*)(row + 4) = make_float4(f[4], f[5], f[6], f[7]);
    }
}

// ===================== Kernel A: tiled-GEMM radial MLP -> mix =====================
__global__ void __launch_bounds__(TPB_A, 4)
mlp_kernel(const float* __restrict__ radial,
           const float* __restrict__ w1, const float* __restrict__ w2,
           const float* __restrict__ w3, const float* __restrict__ w4,
           int n_edges)
{
    extern __shared__ float smem[];
    float* sA   = smem;            // 4096 used (region spans 4352 incl. pad)
    float* sB   = smem + 4352;     // 4096
    float* sW   = smem + 8448;     // 4096
    float* sMix = smem;            // stride-68 rows, 64*68 = 4352

    int tid = threadIdx.x;
    int e0 = blockIdx.x * TE;
    int eoff = (tid & 31) * 2;    // 32 e-groups of 2 edges
    int joff = (tid >> 5) * 8;    // 8 j-groups of 8 cols (warp-uniform)

    // stage radial transposed into sA[k][e] (k<8); stage w1 concurrently
    if (tid < 128) {
        int e  = tid >> 1;
        int kh = (tid & 1) * 4;
        int ge = e0 + e;
        float4 v = make_float4(0.f, 0.f, 0.f, 0.f);
        if (ge < n_edges) v = *(const float4*)(radial + (size_t)ge * 8 + kh);
        sA[(kh + 0) * 64 + e] = v.x;
        sA[(kh + 1) * 64 + e] = v.y;
        sA[(kh + 2) * 64 + e] = v.z;
        sA[(kh + 3) * 64 + e] = v.w;
    } else {
        int t = tid - 128;                       // 0..127
        ((float4*)sW)[t] = ((const float4*)w1)[t];
    }
    __syncthreads();

    u64 acc[8];

    // layer 1: K=8, scale 1/sqrt(8)
    gemm8<8>(sA, sW, eoff, joff, acc);
    epiT8(acc, 0.35355339059327373f, 1.0f, sB, eoff, joff);
    __syncthreads();

    // layer 2
    #pragma unroll
    for (int i = 0; i < 4; i++)
        ((float4*)sW)[tid + i * TPB_A] = ((const float4*)w2)[tid + i * TPB_A];
    __syncthreads();
    gemm8<64>(sB, sW, eoff, joff, acc);
    epiT8(acc, 0.125f, 1.0f, sA, eoff, joff);
    __syncthreads();

    // layer 3: fold (1/8 w4-norm)*(1/sqrt(16)) = 1/32 into h3
    #pragma unroll
    for (int i = 0; i < 4; i++)
        ((float4*)sW)[tid + i * TPB_A] = ((const float4*)w3)[tid + i * TPB_A];
    __syncthreads();
    gemm8<64>(sA, sW, eoff, joff, acc);
    epiT8(acc, 0.125f, 0.03125f, sB, eoff, joff);
    __syncthreads();

    // layer 4: mix = h3 @ w4, 4 chunks of 64 cols; h3 persists in sB
    #pragma unroll 1
    for (int chunk = 0; chunk < 4; chunk++) {
        #pragma unroll
        for (int i = 0; i < 4; i++) {
            int idx = tid + i * TPB_A;           // 0..1023
            int row = idx >> 4, col = idx & 15;
            ((float4*)sW)[idx] =
                *(const float4*)(w4 + (size_t)row * 256 + chunk * 64 + col * 4);
        }
        __syncthreads();
        gemm8<64>(sB, sW, eoff, joff, acc);
        epiMix8(acc, sMix, eoff, joff);
        __syncthreads();
        // coalesced copy sMix -> g_mix chunk
        #pragma unroll
        for (int i = 0; i < 4; i++) {
            int idx = tid + i * TPB_A;           // float4 idx 0..1023
            int row = idx >> 4, col = idx & 15;
            int ge = e0 + row;
            if (ge < n_edges)
                *(float4*)(g_mix + (size_t)ge * 256 + chunk * 64 + col * 4) =
                    ((float4*)(sMix + row * MIX_STRIDE))[col];
        }
        __syncthreads();
    }
}

// ===================== Kernel B: tensor product + coalesced scatter =====================
// Position p in [0,1024): irrep regions
//   r0 [0,64)    W=1
//   r1 [64,256)  W=3  tbase=64  ybase=0
//   r2 [256,576) W=5  tbase=128 ybase=3
//   r3 [576,1024)W=7  tbase=192 ybase=8
template<int W, int START, int TB, int YB, int MUL>
__device__ __forceinline__ float tpv(const float* tsh, const float* ysh, int p) {
    int pp = p - START;
    int c = (pp * MUL) >> 16;
    int k = pp - c * W;
    return tsh[TB + c] * ysh[YB + k];
}

#define TPB_B 256

__global__ void __launch_bounds__(TPB_B)
scatter_kernel(const float* __restrict__ vectors,
               const float* __restrict__ node_feats,
               const int* __restrict__ senders,
               const int* __restrict__ receivers,
               float* __restrict__ out, int n_edges)
{
    __shared__ float stage[TPB_B / 32][272];   // per-warp: t[256] + y[15]
    int warp = threadIdx.x >> 5, lane = threadIdx.x & 31;
    int e = blockIdx.x * (TPB_B / 32) + warp;
    if (e >= n_edges) return;

    float* tsh = stage[warp];
    float* ysh = tsh + 256;

    int snd = __ldg(senders + e), rcv = __ldg(receivers + e);

    // t[c] = node_feats[snd][c & 63] * mix[e][c]
    {
        const float4* mp = (const float4*)(g_mix + (size_t)e * 256) + lane * 2;
        float4 m0 = __ldg(mp), m1 = __ldg(mp + 1);
        const float4* sp = (const float4*)(node_feats + (size_t)snd * 64) + (lane & 7) * 2;
        float4 s0 = __ldg(sp), s1 = __ldg(sp + 1);
        float4 t0 = make_float4(m0.x*s0.x, m0.y*s0.y, m0.z*s0.z, m0.w*s0.w);
        float4 t1 = make_float4(m1.x*s1.x, m1.y*s1.y, m1.z*s1.z, m1.w*s1.w);
        ((float4*)tsh)[lane*2]     = t0;
        ((float4*)tsh)[lane*2 + 1] = t1;
    }

    // spherical harmonics (lane 0 stores 15 floats)
    {
        float vx = __ldg(vectors + 3*(size_t)e + 0);
        float vy = __ldg(vectors + 3*(size_t)e + 1);
        float vz = __ldg(vectors + 3*(size_t)e + 2);
        float inv = 1.0f / (sqrtf(vx*vx + vy*vy + vz*vz) + 1e-12f);
        float x = vx*inv, y = vy*inv, z = vz*inv;
        const float s3  = 1.7320508075688772f;
        const float s5  = 2.23606797749979f;
        const float s15 = 3.872983346207417f;
        const float c33 = 2.091650066335189f;
        const float c32 = 10.246950765959598f;
        const float c31 = 1.6201851746019651f;
        const float c30 = 1.3228756555322954f;
        float z2 = z*z, x2 = x*x, y2 = y*y;
        if (lane == 0) {
            ysh[0]  = s3 * y;  ysh[1] = s3 * z;  ysh[2] = s3 * x;
            ysh[3]  = s15 * x * y;
            ysh[4]  = s15 * y * z;
            ysh[5]  = 0.5f * s5 * (3.0f * z2 - 1.0f);
            ysh[6]  = s15 * x * z;
            ysh[7]  = 0.5f * s15 * (x2 - y2);
            ysh[8]  = c33 * y * (3.0f * x2 - y2);
            ysh[9]  = c32 * x * y * z;
            ysh[10] = c31 * y * (5.0f * z2 - 1.0f);
            ysh[11] = c30 * z * (5.0f * z2 - 3.0f);
            ysh[12] = c31 * x * (5.0f * z2 - 1.0f);
            ysh[13] = 0.5f * c32 * z * (x2 - y2);
            ysh[14] = c33 * x * (x2 - 3.0f * y2);
        }
    }
    __syncwarp();

    float* ob = out + (size_t)rcv * 1024;

    #pragma unroll
    for (int j = 0; j < 8; j++) {
        int p0 = j * 128 + lane * 4;
        float v0, v1, v2, v3;
        if (j == 0) {
            if (lane < 16) {
                v0 = tsh[p0]; v1 = tsh[p0+1]; v2 = tsh[p0+2]; v3 = tsh[p0+3];
            } else {
                v0 = tpv<3,64,64,0,21846>(tsh, ysh, p0);
                v1 = tpv<3,64,64,0,21846>(tsh, ysh, p0+1);
                v2 = tpv<3,64,64,0,21846>(tsh, ysh, p0+2);
                v3 = tpv<3,64,64,0,21846>(tsh, ysh, p0+3);
            }
        } else if (j == 1) {
            v0 = tpv<3,64,64,0,21846>(tsh, ysh, p0);
            v1 = tpv<3,64,64,0,21846>(tsh, ysh, p0+1);
            v2 = tpv<3,64,64,0,21846>(tsh, ysh, p0+2);
            v3 = tpv<3,64,64,0,21846>(tsh, ysh, p0+3);
        } else if (j == 2 || j == 3) {
            v0 = tpv<5,256,128,3,13108>(tsh, ysh, p0);
            v1 = tpv<5,256,128,3,13108>(tsh, ysh, p0+1);
            v2 = tpv<5,256,128,3,13108>(tsh, ysh, p0+2);
            v3 = tpv<5,256,128,3,13108>(tsh, ysh, p0+3);
        } else if (j == 4) {
            if (lane < 16) {
                v0 = tpv<5,256,128,3,13108>(tsh, ysh, p0);
                v1 = tpv<5,256,128,3,13108>(tsh, ysh, p0+1);
                v2 = tpv<5,256,128,3,13108>(tsh, ysh, p0+2);
                v3 = tpv<5,256,128,3,13108>(tsh, ysh, p0+3);
            } else {
                v0 = tpv<7,576,192,8,9363>(tsh, ysh, p0);
                v1 = tpv<7,576,192,8,9363>(tsh, ysh, p0+1);
                v2 = tpv<7,576,192,8,9363>(tsh, ysh, p0+2);
                v3 = tpv<7,576,192,8,9363>(tsh, ysh, p0+3);
            }
        } else {
            v0 = tpv<7,576,192,8,9363>(tsh, ysh, p0);
            v1 = tpv<7,576,192,8,9363>(tsh, ysh, p0+1);
            v2 = tpv<7,576,192,8,9363>(tsh, ysh, p0+2);
            v3 = tpv<7,576,192,8,9363>(tsh, ysh, p0+3);
        }
        red4(ob + p0, v0, v1, v2, v3);
    }
}

extern "C" void kernel_launch(void* const* d_in, const int* in_sizes, int n_in,
                              void* d_out, int out_size)
{
    const float* vectors    = (const float*)d_in[0];
    const float* node_feats = (const float*)d_in[1];
    const float* radial     = (const float*)d_in[2];
    const float* w1         = (const float*)d_in[3];
    const float* w2         = (const float*)d_in[4];
    const float* w3         = (const float*)d_in[5];
    const float* w4         = (const float*)d_in[6];
    const int*   senders    = (const int*)d_in[7];
    const int*   receivers  = (const int*)d_in[8];
    float* out = (float*)d_out;

    int n_edges = in_sizes[7];

    cudaFuncSetAttribute(mlp_kernel,
                         cudaFuncAttributeMaxDynamicSharedMemorySize,
                         SMEM_A_FLOATS * sizeof(float));

    cudaMemsetAsync(d_out, 0, (size_t)out_size * sizeof(float));

    int grid_a = (n_edges + TE - 1) / TE;
    mlp_kernel<<<grid_a, TPB_A, SMEM_A_FLOATS * sizeof(float)>>>(
        radial, w1, w2, w3, w4, n_edges);

    int edges_per_blk = TPB_B / 32;
    int grid_b = (n_edges + edges_per_blk - 1) / edges_per_blk;
    scatter_kernel<<<grid_b, TPB_B>>>(vectors, node_feats, senders, receivers,
                                      out, n_edges);
}

// round 12
// speedup vs baseline: 1.1152x; 1.0268x over previous
#include <cuda_runtime.h>
#include <cstdint>

typedef unsigned int u32;

#define N_EDGES_CAP 160000
__device__ float g_mix[(size_t)N_EDGES_CAP * 256];

#define TE 64
#define TPB 128
#define AST 72   // activation tile row stride (floats)
#define WST 72   // weight tile row stride (floats)
// smem: aHi[64*72] aLo[64*72] wHi[64*72] wLo[64*72]
#define SMEM_FLOATS (4 * 64 * 72)

// ---------- tf32 helpers ----------
__device__ __forceinline__ u32 tf32_of(float v) {
    u32 r; asm("cvt.rna.tf32.f32 %0, %1;" : "=r"(r) : "f"(v)); return r;
}
__device__ __forceinline__ void split_tf32(float v, float& hi, float& lo) {
    hi = __uint_as_float(tf32_of(v));
    lo = __uint_as_float(tf32_of(v - hi));
}
__device__ __forceinline__ void mma_tf32(float (&d)[4],
    u32 a0, u32 a1, u32 a2, u32 a3, u32 b0, u32 b1)
{
    asm volatile("mma.sync.aligned.m16n8k8.row.col.f32.tf32.tf32.f32 "
        "{%0,%1,%2,%3}, {%4,%5,%6,%7}, {%8,%9}, {%0,%1,%2,%3};"
        : "+f"(d[0]), "+f"(d[1]), "+f"(d[2]), "+f"(d[3])
        : "r"(a0), "r"(a1), "r"(a2), "r"(a3), "r"(b0), "r"(b1));
}

__device__ __forceinline__ void red4(float* p, float a, float b, float c, float d) {
    asm volatile("red.global.add.v4.f32 [%0], {%1, %2, %3, %4};"
                 :: "l"(p), "f"(a), "f"(b), "f"(c), "f"(d) : "memory");
}
__device__ __forceinline__ float silu(float x) {
    return __fdividef(x, 1.0f + __expf(-x));
}

// ---------- warp GEMM: 16 edges x 64 cols, K = KT*8, split-tf32 (3 products) ----------
template<int KT>
__device__ __forceinline__ void warp_gemm(
    const float* __restrict__ aHi, const float* __restrict__ aLo,
    const float* __restrict__ wHi, const float* __restrict__ wLo,
    int warp, int gid, int tig, float (&d)[8][4])
{
    #pragma unroll
    for (int nt = 0; nt < 8; nt++)
        #pragma unroll
        for (int q = 0; q < 4; q++) d[nt][q] = 0.f;

    const int r0 = (warp * 16 + gid) * AST;
    const int r1 = r0 + 8 * AST;

    #pragma unroll 2
    for (int kt = 0; kt < KT; kt++) {
        const int c0 = kt * 8 + tig, c1 = c0 + 4;
        u32 ah0 = __float_as_uint(aHi[r0 + c0]);
        u32 ah1 = __float_as_uint(aHi[r1 + c0]);
        u32 ah2 = __float_as_uint(aHi[r0 + c1]);
        u32 ah3 = __float_as_uint(aHi[r1 + c1]);
        u32 al0 = __float_as_uint(aLo[r0 + c0]);
        u32 al1 = __float_as_uint(aLo[r1 + c0]);
        u32 al2 = __float_as_uint(aLo[r0 + c1]);
        u32 al3 = __float_as_uint(aLo[r1 + c1]);
        const int kr0 = (kt * 8 + tig) * WST;
        const int kr1 = kr0 + 4 * WST;
        #pragma unroll
        for (int nt = 0; nt < 8; nt++) {
            const int nc = nt * 8 + gid;
            u32 bh0 = __float_as_uint(wHi[kr0 + nc]);
            u32 bh1 = __float_as_uint(wHi[kr1 + nc]);
            u32 bl0 = __float_as_uint(wLo[kr0 + nc]);
            u32 bl1 = __float_as_uint(wLo[kr1 + nc]);
            mma_tf32(d[nt], ah0, ah1, ah2, ah3, bh0, bh1);
            mma_tf32(d[nt], al0, al1, al2, al3, bh0, bh1);
            mma_tf32(d[nt], ah0, ah1, ah2, ah3, bl0, bl1);
        }
    }
}

// inter-layer epilogue: silu(d*scale)*post -> split -> act tiles (in place, own rows)
__device__ __forceinline__ void epi_act(float (&d)[8][4], float scale, float post,
    float* __restrict__ aHi, float* __restrict__ aLo, int warp, int gid, int tig)
{
    const int r0 = (warp * 16 + gid) * AST;
    const int r1 = r0 + 8 * AST;
    #pragma unroll
    for (int nt = 0; nt < 8; nt++) {
        const int c = nt * 8 + 2 * tig;
        float v0 = silu(d[nt][0] * scale) * post;
        float v1 = silu(d[nt][1] * scale) * post;
        float v2 = silu(d[nt][2] * scale) * post;
        float v3 = silu(d[nt][3] * scale) * post;
        float h0,l0,h1,l1,h2,l2,h3,l3;
        split_tf32(v0, h0, l0); split_tf32(v1, h1, l1);
        split_tf32(v2, h2, l2); split_tf32(v3, h3, l3);
        *(float2*)&aHi[r0 + c] = make_float2(h0, h1);
        *(float2*)&aHi[r1 + c] = make_float2(h2, h3);
        *(float2*)&aLo[r0 + c] = make_float2(l0, l1);
        *(float2*)&aLo[r1 + c] = make_float2(l2, l3);
    }
}

// stage a 64x64 weight tile (fp32 src, row stride ld) into hi/lo tf32 tiles
__device__ __forceinline__ void stage_w(const float* __restrict__ w, int ld,
    float* __restrict__ wHi, float* __restrict__ wLo, int tid)
{
    #pragma unroll 8
    for (int i = 0; i < 32; i++) {
        int idx = tid + i * TPB;         // 0..4095
        int k = idx >> 6, n = idx & 63;
        float v = __ldg(w + (size_t)k * ld + n);
        float hi, lo;
        split_tf32(v, hi, lo);
        wHi[k * WST + n] = hi;
        wLo[k * WST + n] = lo;
    }
}

// ===================== Kernel A: tensor-core (HMMA) MLP -> mix =====================
__global__ void __launch_bounds__(TPB)
mlp_tc_kernel(const float* __restrict__ radial,
              const float* __restrict__ w1, const float* __restrict__ w2,
              const float* __restrict__ w3, const float* __restrict__ w4,
              int n_edges)
{
    extern __shared__ float smem[];
    float* aHi = smem;
    float* aLo = smem + 64 * AST;
    float* wHi = smem + 2 * 64 * AST;
    float* wLo = smem + 3 * 64 * AST;

    int tid = threadIdx.x;
    int warp = tid >> 5, lane = tid & 31;
    int gid = lane >> 2, tig = lane & 3;
    int e0 = blockIdx.x * TE;

    // prologue: radial (K=8) split into act tiles
    if (tid < 64) {
        int ge = e0 + tid;
        float4 a = make_float4(0,0,0,0), b = make_float4(0,0,0,0);
        if (ge < n_edges) {
            const float4* rp = (const float4*)(radial + (size_t)ge * 8);
            a = __ldg(rp); b = __ldg(rp + 1);
        }
        float r[8] = {a.x,a.y,a.z,a.w,b.x,b.y,b.z,b.w};
        #pragma unroll
        for (int k = 0; k < 8; k++) {
            float hi, lo; split_tf32(r[k], hi, lo);
            aHi[tid * AST + k] = hi;
            aLo[tid * AST + k] = lo;
        }
    }
    // stage w1 (8x64 = 512)
    #pragma unroll
    for (int i = 0; i < 4; i++) {
        int idx = tid + i * TPB;          // 0..511
        int k = idx >> 6, n = idx & 63;
        float hi, lo; split_tf32(__ldg(w1 + idx), hi, lo);
        wHi[k * WST + n] = hi; wLo[k * WST + n] = lo;
    }
    __syncthreads();

    float d[8][4];

    // ---- layer 1 (K=8, scale 1/sqrt(8)) ----
    warp_gemm<1>(aHi, aLo, wHi, wLo, warp, gid, tig, d);
    epi_act(d, 0.35355339059327373f, 1.0f, aHi, aLo, warp, gid, tig);
    __syncthreads();
    stage_w(w2, 64, wHi, wLo, tid);
    __syncthreads();

    // ---- layer 2 ----
    warp_gemm<8>(aHi, aLo, wHi, wLo, warp, gid, tig, d);
    epi_act(d, 0.125f, 1.0f, aHi, aLo, warp, gid, tig);
    __syncthreads();
    stage_w(w3, 64, wHi, wLo, tid);
    __syncthreads();

    // ---- layer 3 (fold (1/8 w4-norm)*(1/sqrt 16) = 1/32 into h3) ----
    warp_gemm<8>(aHi, aLo, wHi, wLo, warp, gid, tig, d);
    epi_act(d, 0.125f, 0.03125f, aHi, aLo, warp, gid, tig);

    // ---- layer 4: mix = h3 @ w4, 4 chunks of 64 cols ----
    #pragma unroll 1
    for (int c = 0; c < 4; c++) {
        __syncthreads();                  // prior gemm done before W restage
        stage_w(w4 + c * 64, 256, wHi, wLo, tid);
        __syncthreads();
        warp_gemm<8>(aHi, aLo, wHi, wLo, warp, gid, tig, d);
        int er0 = e0 + warp * 16 + gid;
        int er1 = er0 + 8;
        #pragma unroll
        for (int nt = 0; nt < 8; nt++) {
            int col = c * 64 + nt * 8 + 2 * tig;
            if (er0 < n_edges)
                *(float2*)&g_mix[(size_t)er0 * 256 + col] = make_float2(d[nt][0], d[nt][1]);
            if (er1 < n_edges)
                *(float2*)&g_mix[(size_t)er1 * 256 + col] = make_float2(d[nt][2], d[nt][3]);
        }
    }
}

// ===================== Kernel B: tensor product + coalesced scatter =====================
// r0 [0,64) W=1 ; r1 [64,256) W=3 tb=64 yb=0 ; r2 [256,576) W=5 tb=128 yb=3 ;
// r3 [576,1024) W=7 tb=192 yb=8
template<int W, int START, int TB, int YB, int MUL>
__device__ __forceinline__ float tpv(const float* tsh, const float* ysh, int p) {
    int pp = p - START;
    int c = (pp * MUL) >> 16;
    int k = pp - c * W;
    return tsh[TB + c] * ysh[YB + k];
}

#define TPB_B 256

__global__ void __launch_bounds__(TPB_B)
scatter_kernel(const float* __restrict__ vectors,
               const float* __restrict__ node_feats,
               const int* __restrict__ senders,
               const int* __restrict__ receivers,
               float* __restrict__ out, int n_edges)
{
    __shared__ float stage[TPB_B / 32][272];   // per-warp: t[256] + y[15]
    int warp = threadIdx.x >> 5, lane = threadIdx.x & 31;
    int e = blockIdx.x * (TPB_B / 32) + warp;
    if (e >= n_edges) return;

    float* tsh = stage[warp];
    float* ysh = tsh + 256;

    int snd = __ldg(senders + e), rcv = __ldg(receivers + e);

    {
        const float4* mp = (const float4*)(g_mix + (size_t)e * 256) + lane * 2;
        float4 m0 = __ldg(mp), m1 = __ldg(mp + 1);
        const float4* sp = (const float4*)(node_feats + (size_t)snd * 64) + (lane & 7) * 2;
        float4 s0 = __ldg(sp), s1 = __ldg(sp + 1);
        float4 t0 = make_float4(m0.x*s0.x, m0.y*s0.y, m0.z*s0.z, m0.w*s0.w);
        float4 t1 = make_float4(m1.x*s1.x, m1.y*s1.y, m1.z*s1.z, m1.w*s1.w);
        ((float4*)tsh)[lane*2]     = t0;
        ((float4*)tsh)[lane*2 + 1] = t1;
    }

    {
        float vx = __ldg(vectors + 3*(size_t)e + 0);
        float vy = __ldg(vectors + 3*(size_t)e + 1);
        float vz = __ldg(vectors + 3*(size_t)e + 2);
        float inv = 1.0f / (sqrtf(vx*vx + vy*vy + vz*vz) + 1e-12f);
        float x = vx*inv, y = vy*inv, z = vz*inv;
        const float s3  = 1.7320508075688772f;
        const float s5  = 2.23606797749979f;
        const float s15 = 3.872983346207417f;
        const float c33 = 2.091650066335189f;
        const float c32 = 10.246950765959598f;
        const float c31 = 1.6201851746019651f;
        const float c30 = 1.3228756555322954f;
        float z2 = z*z, x2 = x*x, y2 = y*y;
        if (lane == 0) {
            ysh[0]  = s3 * y;  ysh[1] = s3 * z;  ysh[2] = s3 * x;
            ysh[3]  = s15 * x * y;
            ysh[4]  = s15 * y * z;
            ysh[5]  = 0.5f * s5 * (3.0f * z2 - 1.0f);
            ysh[6]  = s15 * x * z;
            ysh[7]  = 0.5f * s15 * (x2 - y2);
            ysh[8]  = c33 * y * (3.0f * x2 - y2);
            ysh[9]  = c32 * x * y * z;
            ysh[10] = c31 * y * (5.0f * z2 - 1.0f);
            ysh[11] = c30 * z * (5.0f * z2 - 3.0f);
            ysh[12] = c31 * x * (5.0f * z2 - 1.0f);
            ysh[13] = 0.5f * c32 * z * (x2 - y2);
            ysh[14] = c33 * x * (x2 - 3.0f * y2);
        }
    }
    __syncwarp();

    float* ob = out + (size_t)rcv * 1024;

    #pragma unroll
    for (int j = 0; j < 8; j++) {
        int p0 = j * 128 + lane * 4;
        float v0, v1, v2, v3;
        if (j == 0) {
            if (lane < 16) {
                v0 = tsh[p0]; v1 = tsh[p0+1]; v2 = tsh[p0+2]; v3 = tsh[p0+3];
            } else {
                v0 = tpv<3,64,64,0,21846>(tsh, ysh, p0);
                v1 = tpv<3,64,64,0,21846>(tsh, ysh, p0+1);
                v2 = tpv<3,64,64,0,21846>(tsh, ysh, p0+2);
                v3 = tpv<3,64,64,0,21846>(tsh, ysh, p0+3);
            }
        } else if (j == 1) {
            v0 = tpv<3,64,64,0,21846>(tsh, ysh, p0);
            v1 = tpv<3,64,64,0,21846>(tsh, ysh, p0+1);
            v2 = tpv<3,64,64,0,21846>(tsh, ysh, p0+2);
            v3 = tpv<3,64,64,0,21846>(tsh, ysh, p0+3);
        } else if (j == 2 || j == 3) {
            v0 = tpv<5,256,128,3,13108>(tsh, ysh, p0);
            v1 = tpv<5,256,128,3,13108>(tsh, ysh, p0+1);
            v2 = tpv<5,256,128,3,13108>(tsh, ysh, p0+2);
            v3 = tpv<5,256,128,3,13108>(tsh, ysh, p0+3);
        } else if (j == 4) {
            if (lane < 16) {
                v0 = tpv<5,256,128,3,13108>(tsh, ysh, p0);
                v1 = tpv<5,256,128,3,13108>(tsh, ysh, p0+1);
                v2 = tpv<5,256,128,3,13108>(tsh, ysh, p0+2);
                v3 = tpv<5,256,128,3,13108>(tsh, ysh, p0+3);
            } else {
                v0 = tpv<7,576,192,8,9363>(tsh, ysh, p0);
                v1 = tpv<7,576,192,8,9363>(tsh, ysh, p0+1);
                v2 = tpv<7,576,192,8,9363>(tsh, ysh, p0+2);
                v3 = tpv<7,576,192,8,9363>(tsh, ysh, p0+3);
            }
        } else {
            v0 = tpv<7,576,192,8,9363>(tsh, ysh, p0);
            v1 = tpv<7,576,192,8,9363>(tsh, ysh, p0+1);
            v2 = tpv<7,576,192,8,9363>(tsh, ysh, p0+2);
            v3 = tpv<7,576,192,8,9363>(tsh, ysh, p0+3);
        }
        red4(ob + p0, v0, v1, v2, v3);
    }
}

extern "C" void kernel_launch(void* const* d_in, const int* in_sizes, int n_in,
                              void* d_out, int out_size)
{
    const float* vectors    = (const float*)d_in[0];
    const float* node_feats = (const float*)d_in[1];
    const float* radial     = (const float*)d_in[2];
    const float* w1         = (const float*)d_in[3];
    const float* w2         = (const float*)d_in[4];
    const float* w3         = (const float*)d_in[5];
    const float* w4         = (const float*)d_in[6];
    const int*   senders    = (const int*)d_in[7];
    const int*   receivers  = (const int*)d_in[8];
    float* out = (float*)d_out;

    int n_edges = in_sizes[7];

    cudaFuncSetAttribute(mlp_tc_kernel,
                         cudaFuncAttributeMaxDynamicSharedMemorySize,
                         SMEM_FLOATS * sizeof(float));

    cudaMemsetAsync(d_out, 0, (size_t)out_size * sizeof(float));

    int grid_a = (n_edges + TE - 1) / TE;
    mlp_tc_kernel<<<grid_a, TPB, SMEM_FLOATS * sizeof(float)>>>(
        radial, w1, w2, w3, w4, n_edges);

    int edges_per_blk = TPB_B / 32;
    int grid_b = (n_edges + edges_per_blk - 1) / edges_per_blk;
    scatter_kernel<<<grid_b, TPB_B>>>(vectors, node_feats, senders, receivers,
                                      out, n_edges);
}

// round 13
// speedup vs baseline: 1.6105x; 1.4440x over previous
#include <cuda_runtime.h>
#include <cstdint>

typedef unsigned int u32;

#define N_EDGES_CAP 160000
__device__ float g_mix[(size_t)N_EDGES_CAP * 256];

#define TE 128
#define TPB_A 256
#define RS 36                         // row stride in u32 (conflict-free: 4*gid+tig)
// u32 offsets: aHi 0 (128*36=4608), aLo 4608, bHi 9216 (64*36=2304), bLo 11520
#define SMEM_U32 13824

// ---------- bf16 split helpers ----------
// pack (v0 -> low half, v1 -> high half) as bf16x2; H = hi parts, L = residual parts
__device__ __forceinline__ void bsplit(float v0, float v1, u32& H, u32& L) {
    asm("cvt.rn.bf16x2.f32 %0, %1, %2;" : "=r"(H) : "f"(v1), "f"(v0));
    float h0 = __uint_as_float(H << 16);
    float h1 = __uint_as_float(H & 0xFFFF0000u);
    asm("cvt.rn.bf16x2.f32 %0, %1, %2;" : "=r"(L) : "f"(v1 - h1), "f"(v0 - h0));
}

__device__ __forceinline__ void mma_bf16(float (&d)[4],
    u32 a0, u32 a1, u32 a2, u32 a3, u32 b0, u32 b1)
{
    asm volatile("mma.sync.aligned.m16n8k16.row.col.f32.bf16.bf16.f32 "
        "{%0,%1,%2,%3}, {%4,%5,%6,%7}, {%8,%9}, {%0,%1,%2,%3};"
        : "+f"(d[0]), "+f"(d[1]), "+f"(d[2]), "+f"(d[3])
        : "r"(a0), "r"(a1), "r"(a2), "r"(a3), "r"(b0), "r"(b1));
}

__device__ __forceinline__ void red4(float* p, float a, float b, float c, float d) {
    asm volatile("red.global.add.v4.f32 [%0], {%1, %2, %3, %4};"
                 :: "l"(p), "f"(a), "f"(b), "f"(c), "f"(d) : "memory");
}
__device__ __forceinline__ float silu(float x) {
    return __fdividef(x, 1.0f + __expf(-x));
}

// ---------- warp GEMM: 32 edges x 32 cols, K = KS*16, split-bf16 (3 products) ----------
template<int KS>
__device__ __forceinline__ void wgemm(const u32* __restrict__ smu,
                                      int m0, int n0, int gid, int tig,
                                      float (&d)[2][4][4])
{
    const u32* aHi = smu;
    const u32* aLo = smu + 4608;
    const u32* bHi = smu + 9216;
    const u32* bLo = smu + 11520;
    #pragma unroll
    for (int mt = 0; mt < 2; mt++)
        #pragma unroll
        for (int nt = 0; nt < 4; nt++)
            #pragma unroll
            for (int q = 0; q < 4; q++) d[mt][nt][q] = 0.f;

    #pragma unroll
    for (int ks = 0; ks < KS; ks++) {
        u32 ah[2][4], al[2][4];
        #pragma unroll
        for (int mt = 0; mt < 2; mt++) {
            int ra = (m0 + mt * 16 + gid) * RS + ks * 8 + tig;
            int rb = ra + 8 * RS;
            ah[mt][0] = aHi[ra];     ah[mt][1] = aHi[rb];
            ah[mt][2] = aHi[ra + 4]; ah[mt][3] = aHi[rb + 4];
            al[mt][0] = aLo[ra];     al[mt][1] = aLo[rb];
            al[mt][2] = aLo[ra + 4]; al[mt][3] = aLo[rb + 4];
        }
        #pragma unroll
        for (int nt = 0; nt < 4; nt++) {
            int rn = (n0 + nt * 8 + gid) * RS + ks * 8 + tig;
            u32 bh0 = bHi[rn], bh1 = bHi[rn + 4];
            u32 bl0 = bLo[rn], bl1 = bLo[rn + 4];
            #pragma unroll
            for (int mt = 0; mt < 2; mt++) {
                mma_bf16(d[mt][nt], ah[mt][0], ah[mt][1], ah[mt][2], ah[mt][3], bh0, bh1);
                mma_bf16(d[mt][nt], al[mt][0], al[mt][1], al[mt][2], al[mt][3], bh0, bh1);
                mma_bf16(d[mt][nt], ah[mt][0], ah[mt][1], ah[mt][2], ah[mt][3], bl0, bl1);
            }
        }
    }
}

// inter-layer epilogue: silu(d*scale)*post -> split-bf16 -> A planes
__device__ __forceinline__ void epi(float (&d)[2][4][4], float scale, float post,
                                    u32* __restrict__ aHi, u32* __restrict__ aLo,
                                    int m0, int n0, int gid, int tig)
{
    #pragma unroll
    for (int mt = 0; mt < 2; mt++) {
        int r0 = (m0 + mt * 16 + gid) * RS, r1 = r0 + 8 * RS;
        #pragma unroll
        for (int nt = 0; nt < 4; nt++) {
            int c2 = (n0 >> 1) + nt * 4 + tig;
            float v00 = silu(d[mt][nt][0] * scale) * post;
            float v01 = silu(d[mt][nt][1] * scale) * post;
            float v10 = silu(d[mt][nt][2] * scale) * post;
            float v11 = silu(d[mt][nt][3] * scale) * post;
            u32 H, L;
            bsplit(v00, v01, H, L); aHi[r0 + c2] = H; aLo[r0 + c2] = L;
            bsplit(v10, v11, H, L); aHi[r1 + c2] = H; aLo[r1 + c2] = L;
        }
    }
}

// stage a 64(k) x 64(n) fp32 weight tile (row-major, stride ld, col offset coff)
// into packed bf16 hi/lo B tiles
__device__ __forceinline__ void stageW64(const float* __restrict__ w, int ld, int coff,
                                         u32* __restrict__ bHi, u32* __restrict__ bLo,
                                         int tid)
{
    #pragma unroll
    for (int i = 0; i < 8; i++) {
        int idx = tid + i * TPB_A;          // 0..2047
        int n = idx & 63, k2 = idx >> 6;    // k2 0..31
        float v0 = __ldg(w + (size_t)(2 * k2) * ld + coff + n);
        float v1 = __ldg(w + (size_t)(2 * k2 + 1) * ld + coff + n);
        u32 H, L; bsplit(v0, v1, H, L);
        bHi[n * RS + k2] = H;
        bLo[n * RS + k2] = L;
    }
}

// ===================== Kernel A: bf16 HMMA MLP -> mix =====================
__global__ void __launch_bounds__(TPB_A, 2)
mlp_tc_kernel(const float* __restrict__ radial,
              const float* __restrict__ w1, const float* __restrict__ w2,
              const float* __restrict__ w3, const float* __restrict__ w4,
              int n_edges)
{
    extern __shared__ u32 smu[];
    u32* aHi = smu;
    u32* aLo = smu + 4608;
    u32* bHi = smu + 9216;
    u32* bLo = smu + 11520;

    int tid = threadIdx.x;
    int warp = tid >> 5, lane = tid & 31;
    int gid = lane >> 2, tig = lane & 3;
    int m0 = (warp & 3) * 32;      // 4 M-warps
    int n0 = (warp >> 2) * 32;     // 2 N-warps
    int e0 = blockIdx.x * TE;

    // ---- prologue: radial -> A (K=8 padded to 16); w1 -> B (k2 0..7, padded) ----
    if (tid < 128) {
        int ge = e0 + tid;
        float4 a = make_float4(0,0,0,0), b = make_float4(0,0,0,0);
        if (ge < n_edges) {
            const float4* rp = (const float4*)(radial + (size_t)ge * 8);
            a = __ldg(rp); b = __ldg(rp + 1);
        }
        int r = tid * RS;
        u32 H, L;
        bsplit(a.x, a.y, H, L); aHi[r + 0] = H; aLo[r + 0] = L;
        bsplit(a.z, a.w, H, L); aHi[r + 1] = H; aLo[r + 1] = L;
        bsplit(b.x, b.y, H, L); aHi[r + 2] = H; aLo[r + 2] = L;
        bsplit(b.z, b.w, H, L); aHi[r + 3] = H; aLo[r + 3] = L;
        #pragma unroll
        for (int k2 = 4; k2 < 8; k2++) { aHi[r + k2] = 0; aLo[r + k2] = 0; }
    } else {
        int t = tid - 128;                   // 0..127 ; 512 entries/plane
        #pragma unroll
        for (int i = 0; i < 4; i++) {
            int idx = t + i * 128;
            int n = idx & 63, k2 = idx >> 6; // k2 0..7
            float v0 = 0.f, v1 = 0.f;
            if (k2 < 4) {
                v0 = __ldg(w1 + (size_t)(2 * k2) * 64 + n);
                v1 = __ldg(w1 + (size_t)(2 * k2 + 1) * 64 + n);
            }
            u32 H, L; bsplit(v0, v1, H, L);
            bHi[n * RS + k2] = H;
            bLo[n * RS + k2] = L;
        }
    }
    __syncthreads();

    float d[2][4][4];

    // ---- layer 1 (K=16 padded, scale 1/sqrt(8)) ----
    wgemm<1>(smu, m0, n0, gid, tig, d);
    __syncthreads();
    epi(d, 0.35355339059327373f, 1.0f, aHi, aLo, m0, n0, gid, tig);
    stageW64(w2, 64, 0, bHi, bLo, tid);
    __syncthreads();

    // ---- layer 2 ----
    wgemm<4>(smu, m0, n0, gid, tig, d);
    __syncthreads();
    epi(d, 0.125f, 1.0f, aHi, aLo, m0, n0, gid, tig);
    stageW64(w3, 64, 0, bHi, bLo, tid);
    __syncthreads();

    // ---- layer 3 (fold (1/8 w4-norm)*(1/sqrt 16) = 1/32 into h3) ----
    wgemm<4>(smu, m0, n0, gid, tig, d);
    __syncthreads();
    epi(d, 0.125f, 0.03125f, aHi, aLo, m0, n0, gid, tig);
    stageW64(w4, 256, 0, bHi, bLo, tid);
    __syncthreads();

    // ---- layer 4: mix = h3 @ w4, 4 chunks of 64 cols ----
    #pragma unroll 1
    for (int c = 0; c < 4; c++) {
        wgemm<4>(smu, m0, n0, gid, tig, d);
        #pragma unroll
        for (int mt = 0; mt < 2; mt++) {
            int er0 = e0 + m0 + mt * 16 + gid;
            int er1 = er0 + 8;
            #pragma unroll
            for (int nt = 0; nt < 4; nt++) {
                int col = c * 64 + n0 + nt * 8 + 2 * tig;
                if (er0 < n_edges)
                    *(float2*)&g_mix[(size_t)er0 * 256 + col] =
                        make_float2(d[mt][nt][0], d[mt][nt][1]);
                if (er1 < n_edges)
                    *(float2*)&g_mix[(size_t)er1 * 256 + col] =
                        make_float2(d[mt][nt][2], d[mt][nt][3]);
            }
        }
        if (c < 3) {
            __syncthreads();
            stageW64(w4, 256, (c + 1) * 64, bHi, bLo, tid);
            __syncthreads();
        }
    }
}

// ===================== Kernel B: tensor product + coalesced scatter =====================
template<int W, int START, int TB, int YB, int MUL>
__device__ __forceinline__ float tpv(const float* tsh, const float* ysh, int p) {
    int pp = p - START;
    int c = (pp * MUL) >> 16;
    int k = pp - c * W;
    return tsh[TB + c] * ysh[YB + k];
}

#define TPB_B 256

__global__ void __launch_bounds__(TPB_B)
scatter_kernel(const float* __restrict__ vectors,
               const float* __restrict__ node_feats,
               const int* __restrict__ senders,
               const int* __restrict__ receivers,
               float* __restrict__ out, int n_edges)
{
    __shared__ float stage[TPB_B / 32][272];
    int warp = threadIdx.x >> 5, lane = threadIdx.x & 31;
    int e = blockIdx.x * (TPB_B / 32) + warp;
    if (e >= n_edges) return;

    float* tsh = stage[warp];
    float* ysh = tsh + 256;

    int snd = __ldg(senders + e), rcv = __ldg(receivers + e);

    {
        const float4* mp = (const float4*)(g_mix + (size_t)e * 256) + lane * 2;
        float4 m0 = __ldg(mp), m1 = __ldg(mp + 1);
        const float4* sp = (const float4*)(node_feats + (size_t)snd * 64) + (lane & 7) * 2;
        float4 s0 = __ldg(sp), s1 = __ldg(sp + 1);
        float4 t0 = make_float4(m0.x*s0.x, m0.y*s0.y, m0.z*s0.z, m0.w*s0.w);
        float4 t1 = make_float4(m1.x*s1.x, m1.y*s1.y, m1.z*s1.z, m1.w*s1.w);
        ((float4*)tsh)[lane*2]     = t0;
        ((float4*)tsh)[lane*2 + 1] = t1;
    }

    {
        float vx = __ldg(vectors + 3*(size_t)e + 0);
        float vy = __ldg(vectors + 3*(size_t)e + 1);
        float vz = __ldg(vectors + 3*(size_t)e + 2);
        float inv = 1.0f / (sqrtf(vx*vx + vy*vy + vz*vz) + 1e-12f);
        float x = vx*inv, y = vy*inv, z = vz*inv;
        const float s3  = 1.7320508075688772f;
        const float s5  = 2.23606797749979f;
        const float s15 = 3.872983346207417f;
        const float c33 = 2.091650066335189f;
        const float c32 = 10.246950765959598f;
        const float c31 = 1.6201851746019651f;
        const float c30 = 1.3228756555322954f;
        float z2 = z*z, x2 = x*x, y2 = y*y;
        if (lane == 0) {
            ysh[0]  = s3 * y;  ysh[1] = s3 * z;  ysh[2] = s3 * x;
            ysh[3]  = s15 * x * y;
            ysh[4]  = s15 * y * z;
            ysh[5]  = 0.5f * s5 * (3.0f * z2 - 1.0f);
            ysh[6]  = s15 * x * z;
            ysh[7]  = 0.5f * s15 * (x2 - y2);
            ysh[8]  = c33 * y * (3.0f * x2 - y2);
            ysh[9]  = c32 * x * y * z;
            ysh[10] = c31 * y * (5.0f * z2 - 1.0f);
            ysh[11] = c30 * z * (5.0f * z2 - 3.0f);
            ysh[12] = c31 * x * (5.0f * z2 - 1.0f);
            ysh[13] = 0.5f * c32 * z * (x2 - y2);
            ysh[14] = c33 * x * (x2 - 3.0f * y2);
        }
    }
    __syncwarp();

    float* ob = out + (size_t)rcv * 1024;

    #pragma unroll
    for (int j = 0; j < 8; j++) {
        int p0 = j * 128 + lane * 4;
        float v0, v1, v2, v3;
        if (j == 0) {
            if (lane < 16) {
                v0 = tsh[p0]; v1 = tsh[p0+1]; v2 = tsh[p0+2]; v3 = tsh[p0+3];
            } else {
                v0 = tpv<3,64,64,0,21846>(tsh, ysh, p0);
                v1 = tpv<3,64,64,0,21846>(tsh, ysh, p0+1);
                v2 = tpv<3,64,64,0,21846>(tsh, ysh, p0+2);
                v3 = tpv<3,64,64,0,21846>(tsh, ysh, p0+3);
            }
        } else if (j == 1) {
            v0 = tpv<3,64,64,0,21846>(tsh, ysh, p0);
            v1 = tpv<3,64,64,0,21846>(tsh, ysh, p0+1);
            v2 = tpv<3,64,64,0,21846>(tsh, ysh, p0+2);
            v3 = tpv<3,64,64,0,21846>(tsh, ysh, p0+3);
        } else if (j == 2 || j == 3) {
            v0 = tpv<5,256,128,3,13108>(tsh, ysh, p0);
            v1 = tpv<5,256,128,3,13108>(tsh, ysh, p0+1);
            v2 = tpv<5,256,128,3,13108>(tsh, ysh, p0+2);
            v3 = tpv<5,256,128,3,13108>(tsh, ysh, p0+3);
        } else if (j == 4) {
            if (lane < 16) {
                v0 = tpv<5,256,128,3,13108>(tsh, ysh, p0);
                v1 = tpv<5,256,128,3,13108>(tsh, ysh, p0+1);
                v2 = tpv<5,256,128,3,13108>(tsh, ysh, p0+2);
                v3 = tpv<5,256,128,3,13108>(tsh, ysh, p0+3);
            } else {
                v0 = tpv<7,576,192,8,9363>(tsh, ysh, p0);
                v1 = tpv<7,576,192,8,9363>(tsh, ysh, p0+1);
                v2 = tpv<7,576,192,8,9363>(tsh, ysh, p0+2);
                v3 = tpv<7,576,192,8,9363>(tsh, ysh, p0+3);
            }
        } else {
            v0 = tpv<7,576,192,8,9363>(tsh, ysh, p0);
            v1 = tpv<7,576,192,8,9363>(tsh, ysh, p0+1);
            v2 = tpv<7,576,192,8,9363>(tsh, ysh, p0+2);
            v3 = tpv<7,576,192,8,9363>(tsh, ysh, p0+3);
        }
        red4(ob + p0, v0, v1, v2, v3);
    }
}

// nop: shifts launch parity so ncu (-s 5 -c 1) captures mlp_tc_kernel next time
__global__ void nop_kernel() {}

extern "C" void kernel_launch(void* const* d_in, const int* in_sizes, int n_in,
                              void* d_out, int out_size)
{
    const float* vectors    = (const float*)d_in[0];
    const float* node_feats = (const float*)d_in[1];
    const float* radial     = (const float*)d_in[2];
    const float* w1         = (const float*)d_in[3];
    const float* w2         = (const float*)d_in[4];
    const float* w3         = (const float*)d_in[5];
    const float* w4         = (const float*)d_in[6];
    const int*   senders    = (const int*)d_in[7];
    const int*   receivers  = (const int*)d_in[8];
    float* out = (float*)d_out;

    int n_edges = in_sizes[7];

    cudaFuncSetAttribute(mlp_tc_kernel,
                         cudaFuncAttributeMaxDynamicSharedMemorySize,
                         SMEM_U32 * sizeof(u32));

    cudaMemsetAsync(d_out, 0, (size_t)out_size * sizeof(float));

    int grid_a = (n_edges + TE - 1) / TE;
    mlp_tc_kernel<<<grid_a, TPB_A, SMEM_U32 * sizeof(u32)>>>(
        radial, w1, w2, w3, w4, n_edges);

    int edges_per_blk = TPB_B / 32;
    int grid_b = (n_edges + edges_per_blk - 1) / edges_per_blk;
    scatter_kernel<<<grid_b, TPB_B>>>(vectors, node_feats, senders, receivers,
                                      out, n_edges);

    nop_kernel<<<1, 32>>>();
}